// round 14
// baseline (speedup 1.0000x reference)
#include <cuda_runtime.h>
#include <cstdint>
#include <cstddef>

#define Tn 1024
#define Bn 512
#define Hn 128
#define In 64
#define G3 384

// 805 MB scratch for precomputed input-side gate projections: xg[b][t][g]
__device__ float g_xg[(size_t)Bn * Tn * G3];

// ---------------------------------------------------------------------------
// Packed f32x2 FMA (Blackwell): d.lo += a.lo*b.lo ; d.hi += a.hi*b.hi
// ---------------------------------------------------------------------------
__device__ __forceinline__ void ffma2(unsigned long long& d,
                                      const unsigned long long a,
                                      const unsigned long long b) {
    asm("fma.rn.f32x2 %0, %1, %2, %0;" : "+l"(d) : "l"(a), "l"(b));
}

__device__ __forceinline__ float hsum2(unsigned long long v) {
    float lo, hi;
    asm("mov.b64 {%0, %1}, %2;" : "=f"(lo), "=f"(hi) : "l"(v));
    return lo + hi;
}

__device__ __forceinline__ float sigf(float x) {
    return __fdividef(1.0f, 1.0f + __expf(-x));
}
__device__ __forceinline__ float tanh_fast(float x) {
    return 1.0f - __fdividef(2.0f, 1.0f + __expf(2.0f * x));
}

// ---------------------------------------------------------------------------
// Kernel 1: xg[r][g] = x[r][:] . W_ih[g][:] + b_ih[g] + (g<256 ? b_hh[g] : 0)
// 64-row x 96-col tiles, 2 blocks/SM (proven ~620us).
// ---------------------------------------------------------------------------
__global__ void __launch_bounds__(256, 2)
xg_gemm(const float* __restrict__ x,
        const float* __restrict__ Wih,
        const float* __restrict__ bih,
        const float* __restrict__ bhh) {
    __shared__ __align__(16) float xs[64 * 64];   // [row][k]
    __shared__ __align__(16) float ws[96 * 68];   // [col][k] padded

    const int tid = threadIdx.x;
    const int r0 = blockIdx.x * 64;
    const int cb = blockIdx.y;       // 0..3 -> 96 gate-cols each

    {
        const float4* xg4 = (const float4*)(x + (size_t)r0 * 64);
        float4* xs4 = (float4*)xs;
        #pragma unroll
        for (int i = tid; i < 64 * 16; i += 256) xs4[i] = xg4[i];
    }
    {
        const float4* wg4 = (const float4*)(Wih + (size_t)cb * 96 * 64);
        #pragma unroll
        for (int i = tid; i < 96 * 16; i += 256) {
            int g = i >> 4, k4 = i & 15;
            *(float4*)(ws + g * 68 + k4 * 4) = wg4[i];
        }
    }
    __syncthreads();

    const int ry = tid >> 4;   // 0..15 -> rows ry*4 .. +4
    const int cx = tid & 15;   // cols cx + 16*jj

    unsigned long long acc[4][6];
    #pragma unroll
    for (int i = 0; i < 4; i++)
        #pragma unroll
        for (int jj = 0; jj < 6; jj++) acc[i][jj] = 0ULL;

    #pragma unroll
    for (int k4 = 0; k4 < 16; k4++) {
        ulonglong2 wv[6];
        #pragma unroll
        for (int jj = 0; jj < 6; jj++)
            wv[jj] = *(const ulonglong2*)(ws + (cx + 16 * jj) * 68 + k4 * 4);
        #pragma unroll
        for (int i = 0; i < 4; i++) {
            ulonglong2 xv = *(const ulonglong2*)(xs + (ry * 4 + i) * 64 + k4 * 4);
            #pragma unroll
            for (int jj = 0; jj < 6; jj++) {
                ffma2(acc[i][jj], xv.x, wv[jj].x);
                ffma2(acc[i][jj], xv.y, wv[jj].y);
            }
        }
    }

    #pragma unroll
    for (int jj = 0; jj < 6; jj++) {
        const int g = cb * 96 + cx + 16 * jj;
        const float bias = bih[g] + (g < 256 ? bhh[g] : 0.0f);
        #pragma unroll
        for (int i = 0; i < 4; i++) {
            const int r = r0 + ry * 4 + i;
            g_xg[(size_t)r * G3 + g] = hsum2(acc[i][jj]) + bias;
        }
    }
}

// ---------------------------------------------------------------------------
// Kernel 2: GRU recurrence + final FC.
// 128 blocks x 4 batches, 384 threads (12 warps, 3/SMSP; reg cap 170).
// Thread: g = tid>>7 (gate), j = tid&127 (hidden unit).
// Each thread holds its FULL W_hh row (128 floats = 64 regs) and computes
// its gate's dot over full k=128 for all 4 batches -> NO k-split, NO
// shuffles; h loads are full-warp broadcasts. Cross-gate combine through
// smem gm[3][4][132] + 2nd barrier; threads g<2 finalize batches {2g,2g+1}.
// h double-buffered. Steady-state smem traffic: h broadcasts only.
// ---------------------------------------------------------------------------
#define HR 132

__global__ void __launch_bounds__(384, 1)
gru_kernel(const float* __restrict__ Whh,
           const float* __restrict__ bhh,
           const float* __restrict__ Wfc,
           const float* __restrict__ bfc,
           float* __restrict__ out) {
    __shared__ __align__(16) float gm[3 * 4 * HR];   // gate partials [g][b][j]
    __shared__ __align__(16) float hs[2 * 4 * HR];   // h double buffer

    const int tid = threadIdx.x;
    const int g = tid >> 7;      // 0..2 gate
    const int j = tid & 127;     // hidden unit
    const int b0 = blockIdx.x * 4;

    // Own W_hh row (gate g, unit j), full k=128 -> 32 ull2 = 64 regs
    ulonglong2 wv[32];
    {
        const ulonglong2* wg = (const ulonglong2*)(Whh + (size_t)(g * 128 + j) * 128);
        #pragma unroll
        for (int kk = 0; kk < 32; kk++) wv[kk] = wg[kk];
    }

    for (int i = tid; i < 4 * HR; i += 384) hs[i] = 0.0f;

    // Combiner state (threads g<2 own batches {2g, 2g+1} of unit j)
    const float bn = bhh[256 + j];
    float hold[2] = {0.f, 0.f};
    const float* xpA = g_xg + ((size_t)(b0 + 2 * g) * Tn) * G3 + j;
    const float* xpB = g_xg + ((size_t)(b0 + 2 * g + 1) * Tn) * G3 + j;

    __syncthreads();

    for (int t = 0; t < Tn; t++) {
        const float* hrd = hs + (t & 1) * (4 * HR);
        float* hwr = hs + ((t & 1) ^ 1) * (4 * HR);

        // Prefetch xg(t) for combiner threads (hidden under the dot)
        float xr0 = 0.f, xz0 = 0.f, xn0 = 0.f, xr1 = 0.f, xz1 = 0.f, xn1 = 0.f;
        if (g < 2) {
            xr0 = xpA[0]; xz0 = xpA[128]; xn0 = xpA[256];
            xr1 = xpB[0]; xz1 = xpB[128]; xn1 = xpB[256];
            xpA += G3; xpB += G3;
        }

        // Dot: gate g, unit j, full k=128, 4 batches. h loads broadcast.
        unsigned long long acc[4] = {0ULL, 0ULL, 0ULL, 0ULL};
        #pragma unroll
        for (int kk = 0; kk < 32; kk++) {
            const ulonglong2 w = wv[kk];
            #pragma unroll
            for (int b = 0; b < 4; b++) {
                ulonglong2 hv = *(const ulonglong2*)(hrd + b * HR + kk * 4);
                ffma2(acc[b], w.x, hv.x);
                ffma2(acc[b], w.y, hv.y);
            }
        }
        #pragma unroll
        for (int b = 0; b < 4; b++)
            gm[(g * 4 + b) * HR + j] = hsum2(acc[b]);

        __syncthreads();   // dot -> combine

        if (g < 2) {
            #pragma unroll
            for (int i = 0; i < 2; i++) {
                const int b = 2 * g + i;
                float hr = gm[(0 * 4 + b) * HR + j];
                float hz = gm[(1 * 4 + b) * HR + j];
                float hn = gm[(2 * 4 + b) * HR + j];
                float xr = i ? xr1 : xr0;
                float xz = i ? xz1 : xz0;
                float xn = i ? xn1 : xn0;
                float r = sigf(xr + hr);
                float z = sigf(xz + hz);
                float n = tanh_fast(fmaf(r, hn + bn, xn));
                float hnew = fmaf(z, hold[i] - n, n);   // (1-z)*n + z*h
                hold[i] = hnew;
                hwr[b * HR + j] = hnew;
            }
        }

        __syncthreads();   // combine -> next dot (also protects gm reuse)
    }

    // Final h in buffer 0 (t=1023 writes buf (1023+1)&1 = 0).
    // FC: out[b][o] = h_T[b] . W_fc[o] + b_fc[o]
    if (tid < 4 * 51) {
        const int b = tid / 51, o = tid % 51;
        float a = bfc[o];
        const float* wf = Wfc + o * 128;
        const float* hp = hs + b * HR;
        #pragma unroll 8
        for (int k = 0; k < 128; k++) a = fmaf(hp[k], wf[k], a);
        out[(b0 + b) * 51 + o] = a;
    }
}

// ---------------------------------------------------------------------------
// Launch
// ---------------------------------------------------------------------------
extern "C" void kernel_launch(void* const* d_in, const int* in_sizes, int n_in,
                              void* d_out, int out_size) {
    const float* x    = (const float*)d_in[0];  // [512,1,1024,64]
    const float* Wih  = (const float*)d_in[1];  // [384,64]
    const float* Whh  = (const float*)d_in[2];  // [384,128]
    const float* bih  = (const float*)d_in[3];  // [384]
    const float* bhh  = (const float*)d_in[4];  // [384]
    const float* Wfc  = (const float*)d_in[5];  // [51,128]
    const float* bfc  = (const float*)d_in[6];  // [51]
    float* out = (float*)d_out;                 // [512,51]

    xg_gemm<<<dim3((Bn * Tn) / 64, 4, 1), 256>>>(x, Wih, bih, bhh);
    gru_kernel<<<128, 384>>>(Whh, bhh, Wfc, bfc, out);
}

// round 15
// speedup vs baseline: 1.5675x; 1.5675x over previous
#include <cuda_runtime.h>
#include <cstdint>
#include <cstddef>

#define Tn 1024
#define Bn 512
#define Hn 128
#define In 64
#define G3 384
#define NTILES 8192          // (Bn*Tn)/64 row-tiles
#define GSTRIDE 74           // persistent grid x-dim (74*2 = 148 SMs * 2 blk)

// 805 MB scratch for precomputed input-side gate projections: xg[b][t][g]
__device__ float g_xg[(size_t)Bn * Tn * G3];

// ---------------------------------------------------------------------------
// Helpers
// ---------------------------------------------------------------------------
__device__ __forceinline__ void ffma2(unsigned long long& d,
                                      const unsigned long long a,
                                      const unsigned long long b) {
    asm("fma.rn.f32x2 %0, %1, %2, %0;" : "+l"(d) : "l"(a), "l"(b));
}

__device__ __forceinline__ float hsum2(unsigned long long v) {
    float lo, hi;
    asm("mov.b64 {%0, %1}, %2;" : "=f"(lo), "=f"(hi) : "l"(v));
    return lo + hi;
}

__device__ __forceinline__ float sigf(float x) {
    return __fdividef(1.0f, 1.0f + __expf(-x));
}
__device__ __forceinline__ float tanh_fast(float x) {
    return 1.0f - __fdividef(2.0f, 1.0f + __expf(2.0f * x));
}

__device__ __forceinline__ uint32_t smem_u32(const void* p) {
    uint32_t a;
    asm("{ .reg .u64 t; cvta.to.shared.u64 t, %1; cvt.u32.u64 %0, t; }"
        : "=r"(a) : "l"(p));
    return a;
}
#define CP_ASYNC16(dst_u32, src_ptr) \
    asm volatile("cp.async.cg.shared.global [%0], [%1], 16;" \
                 :: "r"(dst_u32), "l"(src_ptr))
#define CP_COMMIT() asm volatile("cp.async.commit_group;")
#define CP_WAIT1()  asm volatile("cp.async.wait_group 1;" ::: "memory")

// ---------------------------------------------------------------------------
// Kernel 1 (persistent, pipelined):
// xg[r][g] = x[r][:] . W_ih[g][:] + b_ih[g] + (g<256 ? b_hh[g] : 0)
// Grid 74 x 4 = 296 blocks (2/SM). Block keeps its 96-gate W tile in smem
// for its whole life; loops over ~111 64-row X tiles, double-buffered via
// cp.async. Inner compute = proven 4-row x 6-col FFMA2 thread tile.
// ---------------------------------------------------------------------------
// dynamic smem layout (floats)
#define GX_WS   0                       // [96][68]  = 6528
#define GX_XS   (96 * 68)               // [2][64*64] = 8192
#define GX_FLOATS (GX_XS + 2 * 64 * 64)
#define GX_BYTES  (GX_FLOATS * 4)

__global__ void __launch_bounds__(256, 2)
xg_gemm(const float* __restrict__ x,
        const float* __restrict__ Wih,
        const float* __restrict__ bih,
        const float* __restrict__ bhh) {
    extern __shared__ __align__(16) float smg[];
    float* ws = smg + GX_WS;            // [96][68] padded
    float* xs0 = smg + GX_XS;           // buffer 0
    float* xs1 = xs0 + 64 * 64;         // buffer 1

    const int tid = threadIdx.x;
    const int cb = blockIdx.y;          // 0..3 -> 96 gate-cols

    // One-time W tile load
    {
        const float4* wg4 = (const float4*)(Wih + (size_t)cb * 96 * 64);
        #pragma unroll
        for (int i = tid; i < 96 * 16; i += 256) {
            int g = i >> 4, k4 = i & 15;
            *(float4*)(ws + g * 68 + k4 * 4) = wg4[i];
        }
    }

    const int ry = tid >> 4;   // 0..15 -> rows ry*4 .. +4
    const int cx = tid & 15;   // cols cx + 16*jj

    // Per-thread bias for its 6 gate columns
    float bias[6];
    #pragma unroll
    for (int jj = 0; jj < 6; jj++) {
        const int g = cb * 96 + cx + 16 * jj;
        bias[jj] = bih[g] + (g < 256 ? bhh[g] : 0.0f);
    }

    const uint32_t xs0a = smem_u32(xs0);
    const uint32_t xs1a = smem_u32(xs1);

    // Prefetch first tile into buffer 0 (4 x 16B per thread)
    {
        const float4* src = (const float4*)(x + (size_t)blockIdx.x * 64 * 64);
        #pragma unroll
        for (int i = 0; i < 4; i++) {
            int e = tid + i * 256;
            CP_ASYNC16(xs0a + e * 16, src + e);
        }
    }
    CP_COMMIT();
    __syncthreads();   // W tile visible too

    int buf = 0;
    for (int tile = blockIdx.x; tile < NTILES; tile += GSTRIDE) {
        // Prefetch next tile into the other buffer
        const int ntile = tile + GSTRIDE;
        if (ntile < NTILES) {
            const uint32_t dsta = buf ? xs0a : xs1a;
            const float4* src = (const float4*)(x + (size_t)ntile * 64 * 64);
            #pragma unroll
            for (int i = 0; i < 4; i++) {
                int e = tid + i * 256;
                CP_ASYNC16(dsta + e * 16, src + e);
            }
        }
        CP_COMMIT();
        CP_WAIT1();        // current buffer's group complete
        __syncthreads();

        const float* xs = buf ? xs1 : xs0;

        unsigned long long acc[4][6];
        #pragma unroll
        for (int i = 0; i < 4; i++)
            #pragma unroll
            for (int jj = 0; jj < 6; jj++) acc[i][jj] = 0ULL;

        #pragma unroll
        for (int k4 = 0; k4 < 16; k4++) {
            ulonglong2 wv[6];
            #pragma unroll
            for (int jj = 0; jj < 6; jj++)
                wv[jj] = *(const ulonglong2*)(ws + (cx + 16 * jj) * 68 + k4 * 4);
            #pragma unroll
            for (int i = 0; i < 4; i++) {
                ulonglong2 xv = *(const ulonglong2*)(xs + (ry * 4 + i) * 64 + k4 * 4);
                #pragma unroll
                for (int jj = 0; jj < 6; jj++) {
                    ffma2(acc[i][jj], xv.x, wv[jj].x);
                    ffma2(acc[i][jj], xv.y, wv[jj].y);
                }
            }
        }

        const int r0 = tile * 64;
        #pragma unroll
        for (int jj = 0; jj < 6; jj++) {
            const int g = cb * 96 + cx + 16 * jj;
            #pragma unroll
            for (int i = 0; i < 4; i++) {
                const int r = r0 + ry * 4 + i;
                g_xg[(size_t)r * G3 + g] = hsum2(acc[i][jj]) + bias[jj];
            }
        }

        __syncthreads();   // reads of xs done before next prefetch overwrites
        buf ^= 1;
    }
}

// ---------------------------------------------------------------------------
// Kernel 2: GRU recurrence + final FC. (R12 config — proven 1497 us.)
// 128 blocks x 4 batches, 256 threads, 1 block/SM. Thread: j=tid>>1,
// half=tid&1. r,z gate W row-halves in REGISTERS (128 regs); n gate
// row-half in per-thread-packed smem [tid][68]. h double-buffered;
// 1 barrier/step; cross-half reduction via shfl_xor(.,1).
// ---------------------------------------------------------------------------
#define HROW 136
__device__ __forceinline__ int hpos(int k) { return k + ((k >> 6) << 2); }

// dynamic smem (floats)
#define SM_WN    0                      // [256][68] = 17408 floats
#define SM_HS    (256 * 68)             // [2][4][HROW] = 1088 floats
#define G_SM_FLOATS (SM_HS + 2 * 4 * HROW)
#define G_SM_BYTES  (G_SM_FLOATS * 4)

__global__ void __launch_bounds__(256, 1)
gru_kernel(const float* __restrict__ Whh,
           const float* __restrict__ bhh,
           const float* __restrict__ Wfc,
           const float* __restrict__ bfc,
           float* __restrict__ out) {
    extern __shared__ __align__(16) float sm[];
    float* wn_s = sm + SM_WN;
    float* hs = sm + SM_HS;

    const int tid = threadIdx.x;
    const int j = tid >> 1;
    const int half = tid & 1;
    const int b0 = blockIdx.x * 4;

    // n-gate W_hh row-half -> per-thread packed smem [tid][68]
    {
        const float4* src = (const float4*)(Whh + (size_t)(256 + j) * 128 + half * 64);
        #pragma unroll
        for (int kk = 0; kk < 16; kk++)
            *(float4*)(wn_s + tid * 68 + kk * 4) = src[kk];
    }
    for (int i = tid; i < 4 * HROW; i += 256) hs[i] = 0.0f;

    // r,z gate W row-halves -> registers (2 x 16 ull2 = 128 regs)
    ulonglong2 wrr[16], wzr[16];
    {
        const ulonglong2* wr_g = (const ulonglong2*)(Whh + (size_t)j * 128 + half * 64);
        const ulonglong2* wz_g = (const ulonglong2*)(Whh + (size_t)(j + 128) * 128 + half * 64);
        #pragma unroll
        for (int kk = 0; kk < 16; kk++) {
            wrr[kk] = wr_g[kk];
            wzr[kk] = wz_g[kk];
        }
    }
    const float bn = bhh[256 + j];
    float hold[2] = {0.f, 0.f};

    const size_t xgA = ((size_t)(b0 + 2 * half) * Tn) * G3 + j;
    const size_t xgB = ((size_t)(b0 + 2 * half + 1) * Tn) * G3 + j;
    const ulonglong2* wnp = (const ulonglong2*)(wn_s + tid * 68);

    __syncthreads();

    for (int t = 0; t < Tn; t++) {
        const float* hrd = hs + (t & 1) * (4 * HROW);
        float* hwr = hs + ((t & 1) ^ 1) * (4 * HROW);

        const float* xpA = g_xg + xgA + (size_t)t * G3;
        const float* xpB = g_xg + xgB + (size_t)t * G3;
        float xr0 = xpA[0], xz0 = xpA[128], xn0 = xpA[256];
        float xr1 = xpB[0], xz1 = xpB[128], xn1 = xpB[256];

        unsigned long long acc[3][4];
        #pragma unroll
        for (int g = 0; g < 3; g++)
            #pragma unroll
            for (int b = 0; b < 4; b++) acc[g][b] = 0ULL;

        const float* hbase = hrd + half * 68;
        #pragma unroll
        for (int kk = 0; kk < 16; kk++) {
            const ulonglong2 wr = wrr[kk], wz = wzr[kk];
            const ulonglong2 wn = wnp[kk];
            #pragma unroll
            for (int b = 0; b < 4; b++) {
                ulonglong2 hv = *(const ulonglong2*)(hbase + b * HROW + kk * 4);
                ffma2(acc[0][b], wr.x, hv.x); ffma2(acc[0][b], wr.y, hv.y);
                ffma2(acc[1][b], wz.x, hv.x); ffma2(acc[1][b], wz.y, hv.y);
                ffma2(acc[2][b], wn.x, hv.x); ffma2(acc[2][b], wn.y, hv.y);
            }
        }

        float s[3][4];
        #pragma unroll
        for (int g = 0; g < 3; g++)
            #pragma unroll
            for (int b = 0; b < 4; b++) s[g][b] = hsum2(acc[g][b]);

        float tot[3][2];
        #pragma unroll
        for (int g = 0; g < 3; g++) {
            #pragma unroll
            for (int i = 0; i < 2; i++) {
                float keepv = half ? s[g][2 + i] : s[g][i];
                float sendv = half ? s[g][i] : s[g][2 + i];
                tot[g][i] = keepv + __shfl_xor_sync(0xFFFFFFFFu, sendv, 1);
            }
        }

        {
            float r0g = sigf(xr0 + tot[0][0]);
            float z0g = sigf(xz0 + tot[1][0]);
            float n0g = tanh_fast(fmaf(r0g, tot[2][0] + bn, xn0));
            float h0n = fmaf(z0g, hold[0] - n0g, n0g);
            hold[0] = h0n;
            hwr[(2 * half + 0) * HROW + hpos(j)] = h0n;

            float r1g = sigf(xr1 + tot[0][1]);
            float z1g = sigf(xz1 + tot[1][1]);
            float n1g = tanh_fast(fmaf(r1g, tot[2][1] + bn, xn1));
            float h1n = fmaf(z1g, hold[1] - n1g, n1g);
            hold[1] = h1n;
            hwr[(2 * half + 1) * HROW + hpos(j)] = h1n;
        }

        __syncthreads();
    }

    // Final h is in buffer 0. FC: out[b][o] = h_T[b] . W_fc[o] + b_fc[o]
    if (tid < 4 * 51) {
        const int b = tid / 51, o = tid % 51;
        float a = bfc[o];
        const float* wf = Wfc + o * 128;
        const float* hp = hs + b * HROW;
        #pragma unroll 8
        for (int k = 0; k < 128; k++) a = fmaf(hp[hpos(k)], wf[k], a);
        out[(b0 + b) * 51 + o] = a;
    }
}

// ---------------------------------------------------------------------------
// Launch
// ---------------------------------------------------------------------------
extern "C" void kernel_launch(void* const* d_in, const int* in_sizes, int n_in,
                              void* d_out, int out_size) {
    const float* x    = (const float*)d_in[0];  // [512,1,1024,64]
    const float* Wih  = (const float*)d_in[1];  // [384,64]
    const float* Whh  = (const float*)d_in[2];  // [384,128]
    const float* bih  = (const float*)d_in[3];  // [384]
    const float* bhh  = (const float*)d_in[4];  // [384]
    const float* Wfc  = (const float*)d_in[5];  // [51,128]
    const float* bfc  = (const float*)d_in[6];  // [51]
    float* out = (float*)d_out;                 // [512,51]

    static int attr_done = 0;
    if (!attr_done) {
        cudaFuncSetAttribute(xg_gemm,
                             cudaFuncAttributeMaxDynamicSharedMemorySize,
                             GX_BYTES);
        cudaFuncSetAttribute(gru_kernel,
                             cudaFuncAttributeMaxDynamicSharedMemorySize,
                             G_SM_BYTES);
        attr_done = 1;
    }

    xg_gemm<<<dim3(GSTRIDE, 4, 1), 256, GX_BYTES>>>(x, Wih, bih, bhh);
    gru_kernel<<<128, 256, G_SM_BYTES>>>(Whh, bhh, Wfc, bfc, out);
}